// round 3
// baseline (speedup 1.0000x reference)
#include <cuda_runtime.h>
#include <cuda_bf16.h>
#include <cstdint>

// Problem dims (fixed for this dataset entry)
#define BB 8
#define NN 2048
#define DD 128
#define NROWS (BB * NN)   // 16384

// ---------------- scratch (device globals; no allocation allowed) ----------
__device__ float    g_Wh  [NROWS * DD];      // 8 MB
__device__ float    g_Wh1 [NROWS];
__device__ float    g_Wh2 [NROWS];
__device__ float    g_E1p [NROWS];
__device__ float    g_E1n [NROWS];
__device__ float    g_E2p [NROWS];
__device__ float    g_E2n [NROWS];
__device__ float    g_sinv[NROWS];
__device__ unsigned g_mask[NROWS * (NN / 32)];  // 4 MB bitmask of adj>0

__device__ __forceinline__ float tf32r(float x) {
    unsigned u;
    asm("cvt.rna.tf32.f32 %0, %1;" : "=r"(u) : "f"(x));
    return __uint_as_float(u);
}

__device__ __forceinline__ void mma_tf32(float c[4], const unsigned a[4],
                                         unsigned b0, unsigned b1) {
    asm volatile(
        "mma.sync.aligned.m16n8k8.row.col.f32.tf32.tf32.f32 "
        "{%0,%1,%2,%3}, {%4,%5,%6,%7}, {%8,%9}, {%0,%1,%2,%3};\n"
        : "+f"(c[0]), "+f"(c[1]), "+f"(c[2]), "+f"(c[3])
        : "r"(a[0]), "r"(a[1]), "r"(a[2]), "r"(a[3]), "r"(b0), "r"(b1));
}

// ---------------- K1: Wh = h @ W  (fp32, tiled) -----------------------------
// grid 256 blocks x 256 threads; each block: 64 rows x 128 cols, K=128.
__global__ __launch_bounds__(256) void k1_wh(const float* __restrict__ h,
                                             const float* __restrict__ W) {
    __shared__ float sA[32][64];    // [k][m] (transposed for LDS.128 on rows)
    __shared__ float sW[32][128];   // [k][c]
    const int tid = threadIdx.x;
    const int m0  = blockIdx.x * 64;
    const int r0  = (tid >> 5) << 3;   // 8 rows
    const int c0  = (tid & 31) << 2;   // 4 cols

    float acc[8][4];
#pragma unroll
    for (int i = 0; i < 8; i++)
#pragma unroll
        for (int j = 0; j < 4; j++) acc[i][j] = 0.f;

    for (int kt = 0; kt < 128; kt += 32) {
#pragma unroll
        for (int x = tid; x < 64 * 32; x += 256) {
            int m = x >> 5, k = x & 31;
            sA[k][m] = h[(size_t)(m0 + m) * 128 + kt + k];
        }
#pragma unroll
        for (int x = tid; x < 32 * 128; x += 256) {
            int k = x >> 7, c = x & 127;
            sW[k][c] = W[(kt + k) * 128 + c];
        }
        __syncthreads();
#pragma unroll
        for (int k = 0; k < 32; k++) {
            float a[8], w[4];
#pragma unroll
            for (int i = 0; i < 8; i++) a[i] = sA[k][r0 + i];
#pragma unroll
            for (int j = 0; j < 4; j++) w[j] = sW[k][c0 + j];
#pragma unroll
            for (int i = 0; i < 8; i++)
#pragma unroll
                for (int j = 0; j < 4; j++) acc[i][j] = fmaf(a[i], w[j], acc[i][j]);
        }
        __syncthreads();
    }
#pragma unroll
    for (int i = 0; i < 8; i++)
#pragma unroll
        for (int j = 0; j < 4; j++)
            g_Wh[(size_t)(m0 + r0 + i) * 128 + c0 + j] = acc[i][j];
}

// ---------------- K2: per-row Wh1/Wh2 + factored exps -----------------------
// one warp per row
__global__ __launch_bounds__(256) void k2_rowstats(const float* __restrict__ a) {
    const int row  = blockIdx.x * 8 + (threadIdx.x >> 5);
    const int lane = threadIdx.x & 31;
    const float* wh = g_Wh + (size_t)row * 128;
    float s1 = 0.f, s2 = 0.f;
#pragma unroll
    for (int k = lane; k < 128; k += 32) {
        float v = wh[k];
        s1 = fmaf(v, a[k], s1);
        s2 = fmaf(v, a[128 + k], s2);
    }
#pragma unroll
    for (int o = 16; o; o >>= 1) {
        s1 += __shfl_xor_sync(0xffffffffu, s1, o);
        s2 += __shfl_xor_sync(0xffffffffu, s2, o);
    }
    if (lane == 0) {
        g_Wh1[row] = s1;
        g_Wh2[row] = s2;
        g_E1p[row] = expf(s1);
        g_E1n[row] = expf(0.2f * s1);
        g_E2p[row] = expf(s2);
        g_E2n[row] = expf(0.2f * s2);
    }
}

// ---------------- K3: softmax denominators + adj bitmask --------------------
// grid (N/8, B); one warp per row i; smem holds per-batch j-arrays.
__global__ __launch_bounds__(256) void k3_denom(const int* __restrict__ adj) {
    __shared__ float sW2[NN], sP[NN], sN[NN];
    const int batch = blockIdx.y;
    const int i     = blockIdx.x * 8 + (threadIdx.x >> 5);
    const int lane  = threadIdx.x & 31;
    const int row   = batch * NN + i;

    for (int j = threadIdx.x; j < NN; j += 256) {
        int jr = batch * NN + j;
        sW2[j] = g_Wh2[jr];
        sP[j]  = g_E2p[jr];
        sN[j]  = g_E2n[jr];
    }
    __syncthreads();

    const float w1 = g_Wh1[row];
    float accP = 0.f, accN = 0.f;
    const int* arow = adj + (size_t)row * NN;
    unsigned*  mrow = g_mask + (size_t)row * (NN / 32);

    for (int j0 = 0; j0 < NN; j0 += 32) {
        int av = arow[j0 + lane];
        unsigned m = __ballot_sync(0xffffffffu, av > 0);
        if (lane == 0) mrow[j0 >> 5] = m;
        if (av > 0) {
            int j = j0 + lane;
            if (w1 + sW2[j] >= 0.f) accP += sP[j];
            else                    accN += sN[j];
        }
    }
#pragma unroll
    for (int o = 16; o; o >>= 1) {
        accP += __shfl_xor_sync(0xffffffffu, accP, o);
        accN += __shfl_xor_sync(0xffffffffu, accN, o);
    }
    if (lane == 0) {
        float s = g_E1p[row] * accP + g_E1n[row] * accN;
        g_sinv[row] = (s > 0.f) ? (1.0f / s) : 0.f;
    }
}

// ---------------- K4: fused attention write + (p @ Wh) tf32 MMA -------------
// grid = B * (N/128) = 128 blocks, 256 threads (8 warps).
// Block tile: 128 rows(i) x 128 cols(d); K loop over j in tiles of 128.
#define SP_STRIDE  132
#define SWH_STRIDE 136
#define SMEM_F_COUNT (128 * SP_STRIDE + 128 * SWH_STRIDE + 4 * 128 + 3 * 128 + 512)
#define SMEM_BYTES (SMEM_F_COUNT * 4)

__global__ __launch_bounds__(256) void k4_fused(const float* __restrict__ h,
                                                float* __restrict__ outO,
                                                float* __restrict__ outA) {
    extern __shared__ float smem[];
    float*    sPm   = smem;                       // 128 x 132
    float*    sWh   = sPm  + 128 * SP_STRIDE;     // 128 x 136
    float*    sWh1  = sWh  + 128 * SWH_STRIDE;    // 128
    float*    sE1p  = sWh1 + 128;
    float*    sE1n  = sE1p + 128;
    float*    sInv  = sE1n + 128;
    float*    sW2   = sInv + 128;                 // per j-tile
    float*    sE2p  = sW2  + 128;
    float*    sE2n  = sE2p + 128;
    unsigned* sMask = (unsigned*)(sE2n + 128);    // 128 x 4 words

    const int batch = blockIdx.x >> 4;
    const int i0    = (blockIdx.x & 15) << 7;
    const int tid   = threadIdx.x;
    const int warp  = tid >> 5, lane = tid & 31;
    const int wm    = warp & 3;       // M: 4 warps x 32 rows
    const int wn    = warp >> 2;      // N: 2 warps x 64 cols
    const int g     = lane >> 2, t4 = lane & 3;

    for (int r = tid; r < 128; r += 256) {
        int row = batch * NN + i0 + r;
        sWh1[r] = g_Wh1[row];
        sE1p[r] = g_E1p[row];
        sE1n[r] = g_E1n[row];
        sInv[r] = g_sinv[row];
    }

    float acc[2][8][4];
#pragma unroll
    for (int am = 0; am < 2; am++)
#pragma unroll
        for (int bn = 0; bn < 8; bn++)
#pragma unroll
            for (int q = 0; q < 4; q++) acc[am][bn][q] = 0.f;

    for (int jt = 0; jt < 16; jt++) {
        const int j0 = jt << 7;
        __syncthreads();  // previous iter's MMA reads done before smem reuse

        for (int c = tid; c < 128; c += 256) {
            int jr = batch * NN + j0 + c;
            sW2[c]  = g_Wh2[jr];
            sE2p[c] = g_E2p[jr];
            sE2n[c] = g_E2n[jr];
        }
        for (int x = tid; x < 512; x += 256) {
            int r = x >> 2, w = x & 3;
            sMask[x] = g_mask[(size_t)(batch * NN + i0 + r) * (NN / 32) + (j0 >> 5) + w];
        }
        // Wh j-tile -> smem (tf32-rounded), 128 x 128 via float4
        for (int x = tid; x < 128 * 32; x += 256) {
            int r = x >> 5, c4 = (x & 31) << 2;
            float4 v = *(const float4*)(g_Wh + (size_t)(batch * NN + j0 + r) * 128 + c4);
            float* dst = sWh + r * SWH_STRIDE + c4;
            dst[0] = tf32r(v.x); dst[1] = tf32r(v.y);
            dst[2] = tf32r(v.z); dst[3] = tf32r(v.w);
        }
        __syncthreads();

        // compute p tile: write attention (fp32 exact) + sP (tf32)
        for (int x = tid; x < 4096; x += 256) {
            int r  = x >> 5;
            int c0 = (x & 31) << 2;
            unsigned mword = sMask[(r << 2) + (c0 >> 5)];
            float w1 = sWh1[r], e1p = sE1p[r], e1n = sE1n[r], inv = sInv[r];
            float p[4];
            float4 sp4;
#pragma unroll
            for (int q = 0; q < 4; q++) {
                int c = c0 + q;
                bool on = (mword >> (c & 31)) & 1u;
                float t = (w1 + sW2[c] >= 0.f) ? e1p * sE2p[c] : e1n * sE2n[c];
                p[q] = on ? t * inv : 0.f;
            }
            sp4.x = tf32r(p[0]); sp4.y = tf32r(p[1]);
            sp4.z = tf32r(p[2]); sp4.w = tf32r(p[3]);
            *(float4*)(sPm + r * SP_STRIDE + c0) = sp4;
            *(float4*)(outA + (size_t)(batch * NN + i0 + r) * NN + j0 + c0) =
                make_float4(p[0], p[1], p[2], p[3]);
        }
        __syncthreads();

        // MMA: M128 x N128 x K128 in m16n8k8 atoms
#pragma unroll
        for (int ks = 0; ks < 16; ks++) {
            const int k0 = ks << 3;
            unsigned A[2][4];
#pragma unroll
            for (int am = 0; am < 2; am++) {
                int rb = wm * 32 + am * 16;
                A[am][0] = __float_as_uint(sPm[(rb + g)     * SP_STRIDE + k0 + t4]);
                A[am][1] = __float_as_uint(sPm[(rb + g + 8) * SP_STRIDE + k0 + t4]);
                A[am][2] = __float_as_uint(sPm[(rb + g)     * SP_STRIDE + k0 + t4 + 4]);
                A[am][3] = __float_as_uint(sPm[(rb + g + 8) * SP_STRIDE + k0 + t4 + 4]);
            }
#pragma unroll
            for (int bn = 0; bn < 8; bn++) {
                int col = wn * 64 + bn * 8 + g;
                unsigned b0 = __float_as_uint(sWh[(k0 + t4)     * SWH_STRIDE + col]);
                unsigned b1 = __float_as_uint(sWh[(k0 + t4 + 4) * SWH_STRIDE + col]);
                mma_tf32(acc[0][bn], A[0], b0, b1);
                mma_tf32(acc[1][bn], A[1], b0, b1);
            }
        }
    }

    // epilogue: out = h + h_prime
#pragma unroll
    for (int am = 0; am < 2; am++)
#pragma unroll
        for (int bn = 0; bn < 8; bn++) {
            int row = wm * 32 + am * 16 + g;
            int col = wn * 64 + bn * 8 + t4 * 2;
            size_t base  = (size_t)(batch * NN + i0 + row) * 128 + col;
            size_t base2 = base + 8 * 128;
            outO[base]      = h[base]      + acc[am][bn][0];
            outO[base + 1]  = h[base + 1]  + acc[am][bn][1];
            outO[base2]     = h[base2]     + acc[am][bn][2];
            outO[base2 + 1] = h[base2 + 1] + acc[am][bn][3];
        }
}

// ---------------- host launch ----------------------------------------------
extern "C" void kernel_launch(void* const* d_in, const int* in_sizes, int n_in,
                              void* d_out, int out_size) {
    const float* h   = (const float*)d_in[0];
    const int*   adj = (const int*)d_in[1];
    const float* W   = (const float*)d_in[2];
    const float* a   = (const float*)d_in[3];
    float* outO = (float*)d_out;
    float* outA = outO + (size_t)BB * NN * DD;

    k1_wh<<<NROWS / 64, 256>>>(h, W);
    k2_rowstats<<<NROWS / 8, 256>>>(a);
    k3_denom<<<dim3(NN / 8, BB), 256>>>(adj);

    cudaFuncSetAttribute(k4_fused, cudaFuncAttributeMaxDynamicSharedMemorySize,
                         SMEM_BYTES);
    k4_fused<<<BB * (NN / 128), 256, SMEM_BYTES>>>(h, outO, outA);
}

// round 4
// speedup vs baseline: 1.3027x; 1.3027x over previous
#include <cuda_runtime.h>
#include <cuda_bf16.h>
#include <cstdint>

// Problem dims (fixed for this dataset entry)
#define BB 8
#define NN 2048
#define DD 128
#define NROWS (BB * NN)   // 16384

// ---------------- scratch (device globals; no allocation allowed) ----------
__device__ float    g_Wh  [NROWS * DD];      // tf32-rounded Wh (8 MB)
__device__ float    g_Wh1 [NROWS];
__device__ float    g_Wh2 [NROWS];
__device__ float    g_E1p [NROWS];
__device__ float    g_E1n [NROWS];
__device__ float    g_E2p [NROWS];
__device__ float    g_E2n [NROWS];
__device__ float    g_sinv[NROWS];
// ballot-permuted adjacency bitmask: word (row, it*4+e) bit L = adj[row][it*128+4L+e]
__device__ unsigned g_mask[NROWS * (NN / 32)];  // 4 MB

__device__ __forceinline__ float tf32r(float x) {
    unsigned u;
    asm("cvt.rna.tf32.f32 %0, %1;" : "=r"(u) : "f"(x));
    return __uint_as_float(u);
}

__device__ __forceinline__ void mma_tf32(float c[4], const unsigned a[4],
                                         unsigned b0, unsigned b1) {
    asm volatile(
        "mma.sync.aligned.m16n8k8.row.col.f32.tf32.tf32.f32 "
        "{%0,%1,%2,%3}, {%4,%5,%6,%7}, {%8,%9}, {%0,%1,%2,%3};\n"
        : "+f"(c[0]), "+f"(c[1]), "+f"(c[2]), "+f"(c[3])
        : "r"(a[0]), "r"(a[1]), "r"(a[2]), "r"(a[3]), "r"(b0), "r"(b1));
}

__device__ __forceinline__ uint32_t saddr(const void* p) {
    return (uint32_t)__cvta_generic_to_shared(p);
}
__device__ __forceinline__ void cp_async16(uint32_t dst, const void* src) {
    asm volatile("cp.async.cg.shared.global [%0], [%1], 16;" :: "r"(dst), "l"(src));
}

// ---------------- K1: Wh = h @ W  (fp32) + row stats + exps -----------------
// grid 256 blocks x 256 threads; each block: 64 rows x 128 cols, K=128.
// Warp w owns rows r0..r0+7 entirely -> warp-reduce row stats in epilogue.
__global__ __launch_bounds__(256) void k1_wh(const float* __restrict__ h,
                                             const float* __restrict__ W,
                                             const float* __restrict__ a) {
    __shared__ float sA[32][64];    // [k][m]
    __shared__ float sW[32][128];   // [k][c]
    const int tid  = threadIdx.x;
    const int m0   = blockIdx.x * 64;
    const int lane = tid & 31;
    const int r0   = (tid >> 5) << 3;   // 8 rows per warp
    const int c0   = lane << 2;         // 4 cols per lane

    float acc[8][4];
#pragma unroll
    for (int i = 0; i < 8; i++)
#pragma unroll
        for (int j = 0; j < 4; j++) acc[i][j] = 0.f;

    for (int kt = 0; kt < 128; kt += 32) {
#pragma unroll
        for (int x = tid; x < 64 * 32; x += 256) {
            int m = x >> 5, k = x & 31;
            sA[k][m] = h[(size_t)(m0 + m) * 128 + kt + k];
        }
#pragma unroll
        for (int x = tid; x < 32 * 128; x += 256) {
            int k = x >> 7, c = x & 127;
            sW[k][c] = W[(kt + k) * 128 + c];
        }
        __syncthreads();
#pragma unroll
        for (int k = 0; k < 32; k++) {
            float av[8], wv[4];
#pragma unroll
            for (int i = 0; i < 8; i++) av[i] = sA[k][r0 + i];
#pragma unroll
            for (int j = 0; j < 4; j++) wv[j] = sW[k][c0 + j];
#pragma unroll
            for (int i = 0; i < 8; i++)
#pragma unroll
                for (int j = 0; j < 4; j++) acc[i][j] = fmaf(av[i], wv[j], acc[i][j]);
        }
        __syncthreads();
    }

    // epilogue A: row stats (full fp32) via warp reduce
    float a1[4], a2[4];
#pragma unroll
    for (int j = 0; j < 4; j++) { a1[j] = a[c0 + j]; a2[j] = a[128 + c0 + j]; }
#pragma unroll
    for (int i = 0; i < 8; i++) {
        float s1 = acc[i][0] * a1[0] + acc[i][1] * a1[1] +
                   acc[i][2] * a1[2] + acc[i][3] * a1[3];
        float s2 = acc[i][0] * a2[0] + acc[i][1] * a2[1] +
                   acc[i][2] * a2[2] + acc[i][3] * a2[3];
#pragma unroll
        for (int o = 16; o; o >>= 1) {
            s1 += __shfl_xor_sync(0xffffffffu, s1, o);
            s2 += __shfl_xor_sync(0xffffffffu, s2, o);
        }
        if (lane == 0) {
            int row = m0 + r0 + i;
            g_Wh1[row] = s1;
            g_Wh2[row] = s2;
            g_E1p[row] = expf(s1);
            g_E1n[row] = expf(0.2f * s1);
            g_E2p[row] = expf(s2);
            g_E2n[row] = expf(0.2f * s2);
        }
    }
    // epilogue B: store Wh already tf32-rounded (only consumer is the MMA B operand)
#pragma unroll
    for (int i = 0; i < 8; i++) {
        float4 v;
        v.x = tf32r(acc[i][0]); v.y = tf32r(acc[i][1]);
        v.z = tf32r(acc[i][2]); v.w = tf32r(acc[i][3]);
        *(float4*)(g_Wh + (size_t)(m0 + r0 + i) * 128 + c0) = v;
    }
}

// ---------------- K3: softmax denominators + permuted adj bitmask -----------
// grid (N/8, B); one warp per row i; int4 streaming loads of adj.
__global__ __launch_bounds__(256) void k3_denom(const int* __restrict__ adj) {
    __shared__ float sW2[NN], sP[NN], sN[NN];
    const int batch = blockIdx.y;
    const int i     = blockIdx.x * 8 + (threadIdx.x >> 5);
    const int lane  = threadIdx.x & 31;
    const int row   = batch * NN + i;

    for (int x = threadIdx.x; x < NN / 4; x += 256) {
        ((float4*)sW2)[x] = ((const float4*)(g_Wh2 + batch * NN))[x];
        ((float4*)sP)[x]  = ((const float4*)(g_E2p + batch * NN))[x];
        ((float4*)sN)[x]  = ((const float4*)(g_E2n + batch * NN))[x];
    }
    __syncthreads();

    const float w1 = g_Wh1[row];
    float accP = 0.f, accN = 0.f;
    const int4* arow = (const int4*)(adj + (size_t)row * NN);
    uint4*      mrow = (uint4*)(g_mask + (size_t)row * (NN / 32));

#pragma unroll 4
    for (int it = 0; it < 16; it++) {
        int4 av = __ldcs(arow + it * 32 + lane);
        int jb = it * 128 + lane * 4;
        float4 w2 = *(const float4*)&sW2[jb];
        float4 pp = *(const float4*)&sP[jb];
        float4 nn = *(const float4*)&sN[jb];
        unsigned b0 = __ballot_sync(0xffffffffu, av.x > 0);
        unsigned b1 = __ballot_sync(0xffffffffu, av.y > 0);
        unsigned b2 = __ballot_sync(0xffffffffu, av.z > 0);
        unsigned b3 = __ballot_sync(0xffffffffu, av.w > 0);
        if (lane == 0) mrow[it] = make_uint4(b0, b1, b2, b3);
        if (av.x > 0) { if (w1 + w2.x >= 0.f) accP += pp.x; else accN += nn.x; }
        if (av.y > 0) { if (w1 + w2.y >= 0.f) accP += pp.y; else accN += nn.y; }
        if (av.z > 0) { if (w1 + w2.z >= 0.f) accP += pp.z; else accN += nn.z; }
        if (av.w > 0) { if (w1 + w2.w >= 0.f) accP += pp.w; else accN += nn.w; }
    }
#pragma unroll
    for (int o = 16; o; o >>= 1) {
        accP += __shfl_xor_sync(0xffffffffu, accP, o);
        accN += __shfl_xor_sync(0xffffffffu, accN, o);
    }
    if (lane == 0) {
        float s = g_E1p[row] * accP + g_E1n[row] * accN;
        g_sinv[row] = (s > 0.f) ? (1.0f / s) : 0.f;
    }
}

// ---------------- K4: fused attention write + (p @ Wh) tf32 MMA -------------
// grid = B * (N/64) = 256 blocks, 256 threads; 2 blocks/SM (smem ~105 KB).
// Block tile: 64 rows(i) x 128 cols(d); K loop over j in tiles of 128.
#define SPS 132
#define SWS 136
#define K4_SMEM_F (64 * SPS + 128 * SWS + 3 * 128)
#define K4_SMEM_B (K4_SMEM_F * 4)

__global__ __launch_bounds__(256) void k4_fused(const float* __restrict__ h,
                                                float* __restrict__ outO,
                                                float* __restrict__ outA) {
    extern __shared__ float smem[];
    float* sPm  = smem;               // 64 x 132 (tf32 p tile)
    float* sWh  = sPm + 64 * SPS;     // 128 x 136 (tf32 Wh tile, cp.async)
    float* sW2j = sWh + 128 * SWS;    // 128 per j-tile
    float* sE2p = sW2j + 128;
    float* sE2n = sE2p + 128;

    const int batch = blockIdx.x >> 5;
    const int i0    = (blockIdx.x & 31) << 6;
    const int tid   = threadIdx.x;
    const int warp  = tid >> 5, lane = tid & 31;
    const int g     = lane >> 2, t4 = lane & 3;
    const int wm    = warp & 1;        // M: 2 warps x 32 rows
    const int wn    = warp >> 1;       // N: 4 warps x 32 cols

    // p-loop mapping: fixed row per thread
    const int pr   = tid & 63;
    const int cgrp = tid >> 6;
    const int brow = batch * NN + i0 + pr;
    const float w1   = g_Wh1[brow];
    const float inv  = g_sinv[brow];
    const float e1pI = g_E1p[brow] * inv;
    const float e1nI = g_E1n[brow] * inv;
    const unsigned* maskrow = g_mask + (size_t)brow * (NN / 32);
    float* aRow = outA + (size_t)brow * NN;
    const float* WhB = g_Wh + (size_t)batch * NN * 128;

    float acc[2][4][4];
#pragma unroll
    for (int am = 0; am < 2; am++)
#pragma unroll
        for (int bn = 0; bn < 4; bn++)
#pragma unroll
            for (int q = 0; q < 4; q++) acc[am][bn][q] = 0.f;

    for (int jt = 0; jt < 16; jt++) {
        const int j0 = jt << 7;
        __syncthreads();  // previous MMA reads done before smem reuse

        // async Wh j-tile (tf32 already) -> smem, overlaps p-compute
#pragma unroll
        for (int x = tid; x < 128 * 32; x += 256) {
            int r = x >> 5, c4 = (x & 31) << 2;
            cp_async16(saddr(sWh + r * SWS + c4),
                       WhB + (size_t)(j0 + r) * 128 + c4);
        }
        asm volatile("cp.async.commit_group;");

        // per-j-tile scalars
        if (tid < 96) {
            int arr = tid >> 5, idx = tid & 31;
            const float* src = (arr == 0 ? g_Wh2 : arr == 1 ? g_E2p : g_E2n)
                               + batch * NN + j0;
            float* dst = (arr == 0 ? sW2j : arr == 1 ? sE2p : sE2n);
            ((float4*)dst)[idx] = ((const float4*)src)[idx];
        }
        uint4 mw = *(const uint4*)(maskrow + jt * 4);
        __syncthreads();

        // compute p tile: attention write (fp32) + sPm (tf32)
#pragma unroll
        for (int q = 0; q < 8; q++) {
            int c   = (cgrp << 5) + (q << 2);
            int bit = (cgrp << 3) + q;
            float4 w2 = *(const float4*)&sW2j[c];
            float4 ep = *(const float4*)&sE2p[c];
            float4 en = *(const float4*)&sE2n[c];
            float p0 = ((mw.x >> bit) & 1u) ? ((w1 + w2.x >= 0.f) ? e1pI * ep.x : e1nI * en.x) : 0.f;
            float p1 = ((mw.y >> bit) & 1u) ? ((w1 + w2.y >= 0.f) ? e1pI * ep.y : e1nI * en.y) : 0.f;
            float p2 = ((mw.z >> bit) & 1u) ? ((w1 + w2.z >= 0.f) ? e1pI * ep.z : e1nI * en.z) : 0.f;
            float p3 = ((mw.w >> bit) & 1u) ? ((w1 + w2.w >= 0.f) ? e1pI * ep.w : e1nI * en.w) : 0.f;
            float4 st;
            st.x = tf32r(p0); st.y = tf32r(p1); st.z = tf32r(p2); st.w = tf32r(p3);
            *(float4*)&sPm[pr * SPS + c] = st;
            __stcs((float4*)(aRow + j0 + c), make_float4(p0, p1, p2, p3));
        }
        asm volatile("cp.async.wait_group 0;");
        __syncthreads();

        // MMA: M64 x N128 x K128 in m16n8k8 atoms
#pragma unroll
        for (int ks = 0; ks < 16; ks++) {
            const int k0 = ks << 3;
            unsigned A[2][4];
#pragma unroll
            for (int am = 0; am < 2; am++) {
                int rb = wm * 32 + am * 16;
                A[am][0] = __float_as_uint(sPm[(rb + g)     * SPS + k0 + t4]);
                A[am][1] = __float_as_uint(sPm[(rb + g + 8) * SPS + k0 + t4]);
                A[am][2] = __float_as_uint(sPm[(rb + g)     * SPS + k0 + t4 + 4]);
                A[am][3] = __float_as_uint(sPm[(rb + g + 8) * SPS + k0 + t4 + 4]);
            }
#pragma unroll
            for (int bn = 0; bn < 4; bn++) {
                int col = wn * 32 + bn * 8 + g;
                unsigned b0 = __float_as_uint(sWh[(k0 + t4)     * SWS + col]);
                unsigned b1 = __float_as_uint(sWh[(k0 + t4 + 4) * SWS + col]);
                mma_tf32(acc[0][bn], A[0], b0, b1);
                mma_tf32(acc[1][bn], A[1], b0, b1);
            }
        }
    }

    // epilogue: out = h + h_prime
#pragma unroll
    for (int am = 0; am < 2; am++)
#pragma unroll
        for (int bn = 0; bn < 4; bn++) {
            int row = i0 + wm * 32 + am * 16 + g;
            int col = wn * 32 + bn * 8 + t4 * 2;
            size_t base  = (size_t)(batch * NN + row) * 128 + col;
            size_t base2 = base + 8 * 128;
            outO[base]      = h[base]      + acc[am][bn][0];
            outO[base + 1]  = h[base + 1]  + acc[am][bn][1];
            outO[base2]     = h[base2]     + acc[am][bn][2];
            outO[base2 + 1] = h[base2 + 1] + acc[am][bn][3];
        }
}

// ---------------- host launch ----------------------------------------------
extern "C" void kernel_launch(void* const* d_in, const int* in_sizes, int n_in,
                              void* d_out, int out_size) {
    const float* h   = (const float*)d_in[0];
    const int*   adj = (const int*)d_in[1];
    const float* W   = (const float*)d_in[2];
    const float* a   = (const float*)d_in[3];
    float* outO = (float*)d_out;
    float* outA = outO + (size_t)BB * NN * DD;

    k1_wh<<<NROWS / 64, 256>>>(h, W, a);
    k3_denom<<<dim3(NN / 8, BB), 256>>>(adj);

    cudaFuncSetAttribute(k4_fused, cudaFuncAttributeMaxDynamicSharedMemorySize,
                         K4_SMEM_B);
    k4_fused<<<BB * (NN / 64), 256, K4_SMEM_B>>>(h, outO, outA);
}